// round 8
// baseline (speedup 1.0000x reference)
#include <cuda_runtime.h>

// Problem dims (fixed by setup_inputs)
#define DD 2048      // D
#define OO 8192      // O
#define TT 4096      // T

#define WR_PARTS 128 // word-dim split for stage 1 (16 words per tile)
#define V_PARTS  32  // d-dim split for stage 2 (64 d-rows per tile)
#define N_OT     8   // o-tiles in stage 2 (1024 floats = 256 float4 each)

// Scratch (allocation-free rule: __device__ globals; zero-initialized at load)
__device__ float g_part_wr[WR_PARTS * DD];   // 1 MB
__device__ float g_part_v[V_PARTS * OO];     // 1 MB
__device__ float g_v[OO];                    // 32 KB
__device__ int   g_cnt[N_OT];                // per-o-tile arrival counters

// ---------------------------------------------------------------------------
// K1: partial weighted row-sums of x (float4).
// grid = (2 col-tiles of 1024 floats, 128 word-tiles of 16), block = 256.
// wr[d] = sum_{word>=1} hrf[DD-word] * x[word,d]
// 16 independent float4 loads per thread -> high MLP, fully coalesced.
// ---------------------------------------------------------------------------
__global__ __launch_bounds__(256)
void k1_partial_wr(const float4* __restrict__ x4, const float* __restrict__ hrf) {
    __shared__ float s_c[16];
    const int col4 = blockIdx.x * 256 + threadIdx.x;   // float4 col 0..511
    const int w0   = blockIdx.y * 16;

    if (threadIdx.x < 16) {
        int word = w0 + threadIdx.x;
        s_c[threadIdx.x] = (word >= 1) ? hrf[DD - word] : 0.0f;  // word 0 -> 0
    }
    __syncthreads();

    float4 acc = make_float4(0.f, 0.f, 0.f, 0.f);
    #pragma unroll
    for (int i = 0; i < 16; ++i) {
        const float4 v = x4[(size_t)(w0 + i) * (DD / 4) + col4];
        const float  c = s_c[i];
        acc.x = fmaf(c, v.x, acc.x);
        acc.y = fmaf(c, v.y, acc.y);
        acc.z = fmaf(c, v.z, acc.z);
        acc.w = fmaf(c, v.w, acc.w);
    }
    reinterpret_cast<float4*>(g_part_wr)[blockIdx.y * (DD / 4) + col4] = acc;
}

// ---------------------------------------------------------------------------
// K2: partial GEMV v = wr @ weights (float4), wr-reduce fused as prologue,
// and the v-reduction fused as a WAIT-FREE last-block-per-o-tile epilogue.
// grid = (8 o-tiles, 32 d-tiles of 64), block = 256.
// ---------------------------------------------------------------------------
__global__ __launch_bounds__(256)
void k2_partial_v(const float4* __restrict__ w4) {
    __shared__ float s_wr[64];
    __shared__ int   s_last;
    const int ot  = blockIdx.x;                 // 0..7
    const int dt  = blockIdx.y;                 // 0..31
    const int o4  = ot * 256 + threadIdx.x;     // float4 idx in O, 0..2047
    const int d0  = dt * 64;

    // Fused wr-reduce: threads 0..63 finalize one wr element each
    // (128 partials, L2-resident, buffer reused by all o-tiles).
    if (threadIdx.x < 64) {
        float w = 0.0f;
        #pragma unroll
        for (int p = 0; p < WR_PARTS; ++p)
            w += g_part_wr[p * DD + d0 + threadIdx.x];
        s_wr[threadIdx.x] = w;
    }
    __syncthreads();

    // Main GEMV stream: 64 float4 loads, 8 KB row stride -> distinct lines.
    float4 acc = make_float4(0.f, 0.f, 0.f, 0.f);
    const float4* __restrict__ wp = w4 + (size_t)d0 * (OO / 4) + o4;
    #pragma unroll 8
    for (int i = 0; i < 64; ++i) {
        const float4 v = __ldcs(&wp[(size_t)i * (OO / 4)]);
        const float  s = s_wr[i];
        acc.x = fmaf(s, v.x, acc.x);
        acc.y = fmaf(s, v.y, acc.y);
        acc.z = fmaf(s, v.z, acc.z);
        acc.w = fmaf(s, v.w, acc.w);
    }
    reinterpret_cast<float4*>(g_part_v)[dt * (OO / 4) + o4] = acc;

    // Wait-free completion detection (threadfenceReduction pattern):
    __threadfence();          // make this thread's partial visible device-wide
    __syncthreads();          // all partials of this block are now fenced
    if (threadIdx.x == 0) {
        int old = atomicAdd(&g_cnt[ot], 1);
        s_last = (old == V_PARTS - 1);
    }
    __syncthreads();

    if (s_last) {
        __threadfence();      // acquire: partials of all 32 producer blocks
        // Reduce this o-tile: 256 float4 outputs, one per thread.
        float4 r = make_float4(0.f, 0.f, 0.f, 0.f);
        #pragma unroll
        for (int p = 0; p < V_PARTS; ++p) {
            const float4 v = reinterpret_cast<const float4*>(g_part_v)[p * (OO / 4) + o4];
            r.x += v.x; r.y += v.y; r.z += v.z; r.w += v.w;
        }
        reinterpret_cast<float4*>(g_v)[o4] = r;
        if (threadIdx.x == 0) g_cnt[ot] = 0;   // self-reset for next replay
    }
}

// ---------------------------------------------------------------------------
// K3: out[t,o] = w_times_init[t,o] + v[o] + bias[t].
// One block = one half-row (1024 consecutive float4s). MLP=4 front-batched
// streaming loads; v segment + bias L1/L2-hot. Proven at ~70% DRAM.
// ---------------------------------------------------------------------------
__global__ __launch_bounds__(256)
void k3_broadcast_add(const float4* __restrict__ w_init,
                      const float* __restrict__ bias,
                      float4* __restrict__ out) {
    const int t    = blockIdx.x >> 1;
    const int half = blockIdx.x & 1;
    const size_t base = (size_t)blockIdx.x * 1024 + threadIdx.x;

    const float b = __ldg(&bias[t]);

    const float4 w0 = __ldcs(&w_init[base]);
    const float4 w1 = __ldcs(&w_init[base + 256]);
    const float4 w2 = __ldcs(&w_init[base + 512]);
    const float4 w3 = __ldcs(&w_init[base + 768]);

    const float4* __restrict__ vp =
        reinterpret_cast<const float4*>(g_v) + half * 1024 + threadIdx.x;
    const float4 v0 = __ldg(&vp[0]);
    const float4 v1 = __ldg(&vp[256]);
    const float4 v2 = __ldg(&vp[512]);
    const float4 v3 = __ldg(&vp[768]);

    float4 r0, r1, r2, r3;
    r0.x = w0.x + v0.x + b; r0.y = w0.y + v0.y + b;
    r0.z = w0.z + v0.z + b; r0.w = w0.w + v0.w + b;
    r1.x = w1.x + v1.x + b; r1.y = w1.y + v1.y + b;
    r1.z = w1.z + v1.z + b; r1.w = w1.w + v1.w + b;
    r2.x = w2.x + v2.x + b; r2.y = w2.y + v2.y + b;
    r2.z = w2.z + v2.z + b; r2.w = w2.w + v2.w + b;
    r3.x = w3.x + v3.x + b; r3.y = w3.y + v3.y + b;
    r3.z = w3.z + v3.z + b; r3.w = w3.w + v3.w + b;

    __stcs(&out[base],       r0);
    __stcs(&out[base + 256], r1);
    __stcs(&out[base + 512], r2);
    __stcs(&out[base + 768], r3);
}

// ---------------------------------------------------------------------------
// Input order (metadata): x[D*D], hrf_weight[D], weights[D*O], bias[T],
//                         w_times_init[T*O].  Output: float32 [T*O].
// ---------------------------------------------------------------------------
extern "C" void kernel_launch(void* const* d_in, const int* in_sizes, int n_in,
                              void* d_out, int out_size) {
    const float* x      = (const float*)d_in[0];
    const float* hrf    = (const float*)d_in[1];
    const float* wts    = (const float*)d_in[2];
    const float* bias   = (const float*)d_in[3];
    const float* w_init = (const float*)d_in[4];
    float* out = (float*)d_out;

    k1_partial_wr<<<dim3(2, WR_PARTS), 256>>>((const float4*)x, hrf);
    k2_partial_v<<<dim3(N_OT, V_PARTS), 256>>>((const float4*)wts);
    k3_broadcast_add<<<TT * 2, 256>>>((const float4*)w_init, bias, (float4*)out);
}

// round 12
// speedup vs baseline: 1.0651x; 1.0651x over previous
#include <cuda_runtime.h>

// Problem dims (fixed by setup_inputs)
#define DD 2048      // D
#define OO 8192      // O
#define TT 4096      // T

#define WR_PARTS 64  // word-dim split for stage 1 (32 words per tile)
#define V_PARTS  16  // d-dim split for stage 2 (128 d per tile)
#define N_OT     32  // o-tiles in stage 2 (256 floats each)

// Scratch (allocation-free rule: __device__ globals; zero-initialized at load)
__device__ float g_part_wr[WR_PARTS * DD];   // 512 KB
__device__ float g_part_v[V_PARTS * OO];     // 512 KB
__device__ float g_v[OO];                    // 32 KB
__device__ int   g_cnt[N_OT];                // per-o-tile arrival counters

// ---------------------------------------------------------------------------
// K1: partial weighted row-sums of x.  (identical to the 65.8us baseline)
// grid = (8 col-tiles, 64 word-tiles), block = 256. 32 words/tile, full unroll.
// wr[d] = sum_{word>=1} hrf[DD-word] * x[word,d]
// ---------------------------------------------------------------------------
__global__ __launch_bounds__(256)
void k1_partial_wr(const float* __restrict__ x, const float* __restrict__ hrf) {
    __shared__ float s_c[32];
    const int col = blockIdx.x * 256 + threadIdx.x;
    const int w0  = blockIdx.y * 32;

    if (threadIdx.x < 32) {
        int word = w0 + threadIdx.x;
        s_c[threadIdx.x] = (word >= 1) ? hrf[DD - word] : 0.0f;  // word 0 -> 0
    }
    __syncthreads();

    float acc = 0.0f;
    #pragma unroll
    for (int i = 0; i < 32; ++i) {
        acc = fmaf(s_c[i], x[(size_t)(w0 + i) * DD + col], acc);
    }
    g_part_wr[blockIdx.y * DD + col] = acc;
}

// ---------------------------------------------------------------------------
// K2: partial GEMV v = wr @ weights.
//   prologue + mainloop: identical to the 65.8us baseline
//   epilogue: wait-free last-block-per-o-tile v-reduction (the exact
//             threadfenceReduction pattern that passed in the R8 run) —
//             replaces the separate k2_reduce_v launch.
// grid = (32 o-tiles, 16 d-tiles of 128), block = 256.
// ---------------------------------------------------------------------------
__global__ __launch_bounds__(256)
void k2_partial_v(const float* __restrict__ weights) {
    __shared__ float s_wr[128];
    __shared__ int   s_last;
    const int ot = blockIdx.x;                 // 0..31
    const int dt = blockIdx.y;                 // 0..15
    const int o  = ot * 256 + threadIdx.x;
    const int d0 = dt * 128;

    // Fused wr-reduce: threads 0..127 finalize one wr element each
    // (64 partials, L2-resident, buffer reused by all o-tiles).
    if (threadIdx.x < 128) {
        float w = 0.0f;
        #pragma unroll
        for (int p = 0; p < WR_PARTS; ++p)
            w += g_part_wr[p * DD + d0 + threadIdx.x];
        s_wr[threadIdx.x] = w;
    }
    __syncthreads();

    float acc = 0.0f;
    const float* __restrict__ wp = weights + (size_t)d0 * OO + o;
    #pragma unroll 16
    for (int i = 0; i < 128; ++i)
        acc = fmaf(s_wr[i], wp[(size_t)i * OO], acc);
    g_part_v[dt * OO + o] = acc;

    // Wait-free completion detection (threadfenceReduction pattern):
    __threadfence();          // make this block's partials visible device-wide
    __syncthreads();
    if (threadIdx.x == 0) {
        int old = atomicAdd(&g_cnt[ot], 1);
        s_last = (old == V_PARTS - 1);
    }
    __syncthreads();

    if (s_last) {
        __threadfence();      // acquire: all 16 producer blocks' partials
        float r = 0.0f;
        #pragma unroll
        for (int p = 0; p < V_PARTS; ++p) r += g_part_v[p * OO + o];
        g_v[o] = r;
        if (threadIdx.x == 0) g_cnt[ot] = 0;   // self-reset for next replay
    }
}

// ---------------------------------------------------------------------------
// K3: out[t,o] = w_times_init[t,o] + v[o] + bias[t].
// Identical to the 65.8us baseline (measured 38.1us, ~70% DRAM).
// One block = one half-row (1024 consecutive float4s); MLP=4 front-batched.
// ---------------------------------------------------------------------------
__global__ __launch_bounds__(256)
void k3_broadcast_add(const float4* __restrict__ w_init,
                      const float* __restrict__ bias,
                      float4* __restrict__ out) {
    const int t    = blockIdx.x >> 1;
    const int half = blockIdx.x & 1;
    const size_t base = (size_t)blockIdx.x * 1024 + threadIdx.x;

    const float b = __ldg(&bias[t]);

    const float4 w0 = __ldcs(&w_init[base]);
    const float4 w1 = __ldcs(&w_init[base + 256]);
    const float4 w2 = __ldcs(&w_init[base + 512]);
    const float4 w3 = __ldcs(&w_init[base + 768]);

    const float4* __restrict__ vp =
        reinterpret_cast<const float4*>(g_v) + half * 1024 + threadIdx.x;
    const float4 v0 = __ldg(&vp[0]);
    const float4 v1 = __ldg(&vp[256]);
    const float4 v2 = __ldg(&vp[512]);
    const float4 v3 = __ldg(&vp[768]);

    float4 r0, r1, r2, r3;
    r0.x = w0.x + v0.x + b; r0.y = w0.y + v0.y + b;
    r0.z = w0.z + v0.z + b; r0.w = w0.w + v0.w + b;
    r1.x = w1.x + v1.x + b; r1.y = w1.y + v1.y + b;
    r1.z = w1.z + v1.z + b; r1.w = w1.w + v1.w + b;
    r2.x = w2.x + v2.x + b; r2.y = w2.y + v2.y + b;
    r2.z = w2.z + v2.z + b; r2.w = w2.w + v2.w + b;
    r3.x = w3.x + v3.x + b; r3.y = w3.y + v3.y + b;
    r3.z = w3.z + v3.z + b; r3.w = w3.w + v3.w + b;

    __stcs(&out[base],       r0);
    __stcs(&out[base + 256], r1);
    __stcs(&out[base + 512], r2);
    __stcs(&out[base + 768], r3);
}

// ---------------------------------------------------------------------------
// Input order (metadata): x[D*D], hrf_weight[D], weights[D*O], bias[T],
//                         w_times_init[T*O].  Output: float32 [T*O].
// ---------------------------------------------------------------------------
extern "C" void kernel_launch(void* const* d_in, const int* in_sizes, int n_in,
                              void* d_out, int out_size) {
    const float* x      = (const float*)d_in[0];
    const float* hrf    = (const float*)d_in[1];
    const float* wts    = (const float*)d_in[2];
    const float* bias   = (const float*)d_in[3];
    const float* w_init = (const float*)d_in[4];
    float* out = (float*)d_out;

    k1_partial_wr<<<dim3(DD / 256, WR_PARTS), 256>>>(x, hrf);
    k2_partial_v<<<dim3(N_OT, V_PARTS), 256>>>(wts);
    k3_broadcast_add<<<TT * 2, 256>>>((const float4*)w_init, bias, (float4*)out);
}

// round 13
// speedup vs baseline: 1.1021x; 1.0347x over previous
#include <cuda_runtime.h>

// Problem dims (fixed by setup_inputs)
#define DD 2048      // D
#define OO 8192      // O
#define TT 4096      // T

#define WR_PARTS 64  // word-dim split for stage 1 (32 words per tile)
#define V_PARTS  16  // d-dim split for stage 2 (128 d per tile)

// Scratch (allocation-free rule: __device__ globals; zero-initialized at load)
__device__ float g_part_wr[WR_PARTS * DD];   // 512 KB
__device__ float g_part_v[V_PARTS * OO];     // 512 KB
__device__ float g_v[OO];                    // 32 KB

// ---------------------------------------------------------------------------
// K1: partial weighted row-sums of x.  (identical to the 65.8us baseline)
// grid = (8 col-tiles, 64 word-tiles), block = 256. 32 words/tile, full unroll.
// wr[d] = sum_{word>=1} hrf[DD-word] * x[word,d]
// ---------------------------------------------------------------------------
__global__ __launch_bounds__(256)
void k1_partial_wr(const float* __restrict__ x, const float* __restrict__ hrf) {
    __shared__ float s_c[32];
    const int col = blockIdx.x * 256 + threadIdx.x;
    const int w0  = blockIdx.y * 32;

    if (threadIdx.x < 32) {
        int word = w0 + threadIdx.x;
        s_c[threadIdx.x] = (word >= 1) ? hrf[DD - word] : 0.0f;  // word 0 -> 0
    }
    __syncthreads();

    float acc = 0.0f;
    #pragma unroll
    for (int i = 0; i < 32; ++i) {
        acc = fmaf(s_c[i], x[(size_t)(w0 + i) * DD + col], acc);
    }
    g_part_wr[blockIdx.y * DD + col] = acc;
}

// ---------------------------------------------------------------------------
// K2: partial GEMV v = wr @ weights, wr-reduction fused as prologue.
// (identical to the 65.8us baseline)
// grid = (32 o-tiles, 16 d-tiles of 128), block = 256.
// ---------------------------------------------------------------------------
__global__ __launch_bounds__(256)
void k2_partial_v(const float* __restrict__ weights) {
    __shared__ float s_wr[128];
    const int o  = blockIdx.x * 256 + threadIdx.x;
    const int d0 = blockIdx.y * 128;

    if (threadIdx.x < 128) {
        float w = 0.0f;
        #pragma unroll
        for (int p = 0; p < WR_PARTS; ++p)
            w += g_part_wr[p * DD + d0 + threadIdx.x];
        s_wr[threadIdx.x] = w;
    }
    __syncthreads();

    float acc = 0.0f;
    const float* __restrict__ wp = weights + (size_t)d0 * OO + o;
    #pragma unroll 16
    for (int i = 0; i < 128; ++i) {
        acc = fmaf(s_wr[i], wp[(size_t)i * OO], acc);
    }
    g_part_v[blockIdx.y * OO + o] = acc;
}

// K2r: reduce 16 partials -> g_v. grid = 32, block = 256.
// (identical to the 65.8us baseline — measured cheaper than fusing)
__global__ __launch_bounds__(256)
void k2_reduce_v() {
    const int o = blockIdx.x * 256 + threadIdx.x;
    float acc = 0.0f;
    #pragma unroll
    for (int p = 0; p < V_PARTS; ++p) acc += g_part_v[p * OO + o];
    g_v[o] = acc;
}

// ---------------------------------------------------------------------------
// K3: out[t,o] = w_times_init[t,o] + v[o] + bias[t].  NEW: MLP = 8.
// One block = one FULL row (2048 consecutive float4s of one t):
//   - 8 front-batched streaming float4 loads per thread (128 B in flight)
//   - single bias load per block
//   - v float4s reused by every row -> L1-hot after first wave
// Grid = TT = 4096 blocks, block = 256.
// ---------------------------------------------------------------------------
__global__ __launch_bounds__(256)
void k3_broadcast_add(const float4* __restrict__ w_init,
                      const float* __restrict__ bias,
                      float4* __restrict__ out) {
    const int t = blockIdx.x;
    const size_t base = (size_t)t * 2048 + threadIdx.x;

    const float b = __ldg(&bias[t]);

    // Front-batched streaming loads (8 independent lines in flight).
    float4 w[8];
    #pragma unroll
    for (int j = 0; j < 8; ++j)
        w[j] = __ldcs(&w_init[base + (size_t)j * 256]);

    const float4* __restrict__ vp =
        reinterpret_cast<const float4*>(g_v) + threadIdx.x;
    float4 r[8];
    #pragma unroll
    for (int j = 0; j < 8; ++j) {
        const float4 v = __ldg(&vp[j * 256]);
        r[j].x = w[j].x + v.x + b;
        r[j].y = w[j].y + v.y + b;
        r[j].z = w[j].z + v.z + b;
        r[j].w = w[j].w + v.w + b;
    }

    #pragma unroll
    for (int j = 0; j < 8; ++j)
        __stcs(&out[base + (size_t)j * 256], r[j]);
}

// ---------------------------------------------------------------------------
// Input order (metadata): x[D*D], hrf_weight[D], weights[D*O], bias[T],
//                         w_times_init[T*O].  Output: float32 [T*O].
// ---------------------------------------------------------------------------
extern "C" void kernel_launch(void* const* d_in, const int* in_sizes, int n_in,
                              void* d_out, int out_size) {
    const float* x      = (const float*)d_in[0];
    const float* hrf    = (const float*)d_in[1];
    const float* wts    = (const float*)d_in[2];
    const float* bias   = (const float*)d_in[3];
    const float* w_init = (const float*)d_in[4];
    float* out = (float*)d_out;

    k1_partial_wr<<<dim3(DD / 256, WR_PARTS), 256>>>(x, hrf);
    k2_partial_v<<<dim3(OO / 256, V_PARTS), 256>>>(wts);
    k2_reduce_v<<<OO / 256, 256>>>();
    k3_broadcast_add<<<TT, 256>>>((const float4*)w_init, bias, (float4*)out);
}